// round 7
// baseline (speedup 1.0000x reference)
#include <cuda_runtime.h>
#include <cstdint>

#define NF 128
#define NH 64
#define MAXN 50000
#define MAXE 800000

// Scratch (allocation-free rule: __device__ globals)
__device__ float g_z[(size_t)MAXN * NH];   // 12.8 MB
__device__ float g_sd[MAXN];
__device__ float g_ss[MAXN];
__device__ int   g_dst[MAXE];
__device__ int   g_src[MAXE];
__device__ int   g_cnt[MAXN];
__device__ int   g_rowstart[MAXN];
__device__ int   g_cursor[MAXN];
__device__ int   g_bsum[1024];
__device__ int4  g_csr[MAXE];              // {src, eidx, h_bits, 0}
__device__ int   g_is32;

#define W_STRIDE 68
#define X_STRIDE 132
__device__ float g_whi[NF * W_STRIDE];
__device__ float g_wlo[NF * W_STRIDE];

// ---------------------------------------------------------------------------
__global__ void zero_kernel(int n_nodes) {
    int i = blockIdx.x * blockDim.x + threadIdx.x;
    if (i < n_nodes) g_cnt[i] = 0;
    if (i == 0) g_is32 = 0;
}

// dtype probe: scan first 4096 odd words; int64 (<2^31 values) -> all zero.
__global__ void detect_kernel(const int* __restrict__ w, int nelem) {
    int found = 0;
    int lim = nelem / 2;
    if (lim > 4096) lim = 4096;
    for (int i = threadIdx.x; i < lim; i += 256)
        found |= w[2 * i + 1];
    if (__syncthreads_or(found) && threadIdx.x == 0) g_is32 = 1;
}

__global__ void convert_kernel(const void* __restrict__ ei, int E) {
    int i = blockIdx.x * blockDim.x + threadIdx.x;
    if (i >= E) return;
    int d, s;
    if (g_is32) {
        const int* p = (const int*)ei;
        d = p[i]; s = p[E + i];
    } else {
        const long long* p = (const long long*)ei;
        d = (int)p[i]; s = (int)p[E + i];
    }
    g_dst[i] = d;
    g_src[i] = s;
    atomicAdd(&g_cnt[d], 1);
}

// ---------------------------------------------------------------------------
// Exclusive scan of g_cnt -> g_rowstart.
__global__ void scanA(int n) {
    __shared__ int s[256];
    int t = threadIdx.x, i = blockIdx.x * 256 + t;
    s[t] = (i < n) ? g_cnt[i] : 0;
    __syncthreads();
    for (int off = 128; off; off >>= 1) {
        if (t < off) s[t] += s[t + off];
        __syncthreads();
    }
    if (t == 0) g_bsum[blockIdx.x] = s[0];
}

__global__ void scanB(int nb) {
    __shared__ int s[256];
    int t = threadIdx.x;
    int v = (t < nb) ? g_bsum[t] : 0;
    s[t] = v; __syncthreads();
    for (int off = 1; off < 256; off <<= 1) {
        int a = (t >= off) ? s[t - off] : 0;
        __syncthreads();
        s[t] += a;
        __syncthreads();
    }
    if (t < nb) g_bsum[t] = s[t] - v;
}

__global__ void scanC(int n) {
    __shared__ int s[256];
    int t = threadIdx.x, i = blockIdx.x * 256 + t;
    int v = (i < n) ? g_cnt[i] : 0;
    s[t] = v; __syncthreads();
    for (int off = 1; off < 256; off <<= 1) {
        int a = (t >= off) ? s[t - off] : 0;
        __syncthreads();
        s[t] += a;
        __syncthreads();
    }
    if (i < n) {
        int start = g_bsum[blockIdx.x] + s[t] - v;
        g_rowstart[i] = start;
        g_cursor[i]   = start;
    }
}

// ---------------------------------------------------------------------------
__device__ __forceinline__ float tf32_rna(float x) {
    unsigned r;
    asm("cvt.rna.tf32.f32 %0, %1;" : "=r"(r) : "f"(x));
    return __uint_as_float(r);
}

__device__ __forceinline__ void mma_tf32(float* c, float4 a, float2 b) {
    asm volatile(
        "mma.sync.aligned.m16n8k8.row.col.f32.tf32.tf32.f32 "
        "{%0,%1,%2,%3}, {%4,%5,%6,%7}, {%8,%9}, {%0,%1,%2,%3};"
        : "+f"(c[0]), "+f"(c[1]), "+f"(c[2]), "+f"(c[3])
        : "r"(__float_as_uint(a.x)), "r"(__float_as_uint(a.y)),
          "r"(__float_as_uint(a.z)), "r"(__float_as_uint(a.w)),
          "r"(__float_as_uint(b.x)), "r"(__float_as_uint(b.y)));
}

// One-time W hi/lo split into device globals.
__global__ void w_split_kernel(const float* __restrict__ W) {
    int i = blockIdx.x * blockDim.x + threadIdx.x;
    if (i >= NF * NH) return;
    int k = i >> 6, n = i & 63;
    float v  = W[i];
    float hi = tf32_rna(v);
    g_whi[k * W_STRIDE + n] = hi;
    g_wlo[k * W_STRIDE + n] = v - hi;
}

// TC GEMM v3: 64-row tile, N split across warp halves, W hi/lo pre-split.
// smem: whi+wlo [128][68]x2 (69.6KB) + x [64][132] (33.8KB) = 103.4KB -> 2 CTA/SM.
#define W_FLOATS (NF * W_STRIDE)
#define SMEM_FLOATS (2 * W_FLOATS + 64 * X_STRIDE)

__global__ void __launch_bounds__(256, 2) gemm_tc_kernel(
    const float* __restrict__ x, const float* __restrict__ aw, int n_nodes)
{
    extern __shared__ float sm[];
    float* whi_s = sm;                    // [128][68]
    float* wlo_s = sm + W_FLOATS;         // [128][68]
    float* xsm   = sm + 2 * W_FLOATS;     // [64][132]
    __shared__ float spart_sd[2][64];
    __shared__ float spart_ss[2][64];

    const int tid  = threadIdx.x;
    const int row0 = blockIdx.x * 64;

    // copy pre-split W (float4, coalesced)
    {
        const float4* src = reinterpret_cast<const float4*>(g_whi);
        float4* dst = reinterpret_cast<float4*>(whi_s);
        for (int i = tid; i < W_FLOATS / 4; i += 256) dst[i] = src[i];
        src = reinterpret_cast<const float4*>(g_wlo);
        dst = reinterpret_cast<float4*>(wlo_s);
        for (int i = tid; i < W_FLOATS / 4; i += 256) dst[i] = src[i];
    }
    // x tile (64 rows)
    for (int i = tid; i < 64 * 32; i += 256) {
        int r = i >> 5, q = (i & 31) << 2;
        int row = row0 + r;
        float4 v = make_float4(0.f, 0.f, 0.f, 0.f);
        if (row < n_nodes)
            v = *reinterpret_cast<const float4*>(&x[(size_t)row * NF + q]);
        *reinterpret_cast<float4*>(&xsm[r * X_STRIDE + q]) = v;
    }
    __syncthreads();

    const int warp = tid >> 5;
    const int lane = tid & 31;
    const int g = lane >> 2;
    const int t = lane & 3;
    const int mrow = (warp & 3) * 16;     // 0,16,32,48
    const int grp  = warp >> 2;           // col group 0/1
    const int c0   = grp * 32;

    float c[4][4];
#pragma unroll
    for (int nt = 0; nt < 4; nt++)
#pragma unroll
        for (int j = 0; j < 4; j++) c[nt][j] = 0.f;

    const float* xrowA = &xsm[(mrow + g) * X_STRIDE];
    const float* xrowB = xrowA + 8 * X_STRIDE;

#pragma unroll
    for (int ks = 0; ks < 16; ks++) {
        int k0 = ks * 8 + t;
        float a0f = xrowA[k0];
        float a1f = xrowB[k0];
        float a2f = xrowA[k0 + 4];
        float a3f = xrowB[k0 + 4];
        float4 ah = make_float4(tf32_rna(a0f), tf32_rna(a1f),
                                tf32_rna(a2f), tf32_rna(a3f));
        float4 al = make_float4(a0f - ah.x, a1f - ah.y,
                                a2f - ah.z, a3f - ah.w);
        const float* bh0 = &whi_s[k0 * W_STRIDE + c0 + g];
        const float* bh1 = bh0 + 4 * W_STRIDE;
        const float* bl0 = &wlo_s[k0 * W_STRIDE + c0 + g];
        const float* bl1 = bl0 + 4 * W_STRIDE;
#pragma unroll
        for (int nt = 0; nt < 4; nt++) {
            float2 bh = make_float2(bh0[nt * 8], bh1[nt * 8]);
            float2 bl = make_float2(bl0[nt * 8], bl1[nt * 8]);
            mma_tf32(c[nt], ah, bh);
            mma_tf32(c[nt], al, bh);
            mma_tf32(c[nt], ah, bl);
        }
    }

    // --- epilogue: z writes + cross-group score reduction ---
    const int row_a = row0 + mrow + g;
    const int row_b = row_a + 8;

    float sdA = 0.f, ssA = 0.f, sdB = 0.f, ssB = 0.f;
#pragma unroll
    for (int nt = 0; nt < 4; nt++) {
        int col = c0 + nt * 8 + 2 * t;
        float a1x = __ldg(&aw[col]),      a1y = __ldg(&aw[col + 1]);
        float a2x = __ldg(&aw[NH + col]), a2y = __ldg(&aw[NH + col + 1]);
        sdA += c[nt][0] * a1x + c[nt][1] * a1y;
        ssA += c[nt][0] * a2x + c[nt][1] * a2y;
        sdB += c[nt][2] * a1x + c[nt][3] * a1y;
        ssB += c[nt][2] * a2x + c[nt][3] * a2y;
    }
#pragma unroll
    for (int off = 2; off; off >>= 1) {
        sdA += __shfl_down_sync(0xffffffffu, sdA, off, 4);
        ssA += __shfl_down_sync(0xffffffffu, ssA, off, 4);
        sdB += __shfl_down_sync(0xffffffffu, sdB, off, 4);
        ssB += __shfl_down_sync(0xffffffffu, ssB, off, 4);
    }
    if (t == 0) {
        spart_sd[grp][mrow + g]     = sdA;
        spart_sd[grp][mrow + 8 + g] = sdB;
        spart_ss[grp][mrow + g]     = ssA;
        spart_ss[grp][mrow + 8 + g] = ssB;
    }

    if (row_a < n_nodes) {
#pragma unroll
        for (int nt = 0; nt < 4; nt++)
            *reinterpret_cast<float2*>(
                &g_z[(size_t)row_a * NH + c0 + nt * 8 + 2 * t]) =
                make_float2(c[nt][0], c[nt][1]);
    }
    if (row_b < n_nodes) {
#pragma unroll
        for (int nt = 0; nt < 4; nt++)
            *reinterpret_cast<float2*>(
                &g_z[(size_t)row_b * NH + c0 + nt * 8 + 2 * t]) =
                make_float2(c[nt][2], c[nt][3]);
    }
    __syncthreads();
    if (tid < 64) {
        int row = row0 + tid;
        if (row < n_nodes) {
            g_sd[row] = spart_sd[0][tid] + spart_sd[1][tid];
            g_ss[row] = spart_ss[0][tid] + spart_ss[1][tid];
        }
    }
}

// ---------------------------------------------------------------------------
__global__ void edge_scatter_kernel(const float* __restrict__ ab, int E) {
    int e = blockIdx.x * blockDim.x + threadIdx.x;
    if (e >= E) return;
    int d = g_dst[e], s = g_src[e];
    float h = g_sd[d] + g_ss[s] + __ldg(ab);
    h = (h >= 0.f) ? h : 0.05f * h;
    h = expf(h);
    int pos = atomicAdd(&g_cursor[d], 1);
    g_csr[pos] = make_int4(s, e, __float_as_int(h), 0);
}

// ---------------------------------------------------------------------------
__global__ void __launch_bounds__(256) aggregate_csr_kernel(
    float* __restrict__ out, float* __restrict__ alpha, int n_nodes)
{
    int w = (blockIdx.x * 256 + threadIdx.x) >> 5;
    int lane = threadIdx.x & 31;
    if (w >= n_nodes) return;

    int start = g_rowstart[w];
    int deg   = g_cnt[w];

    float2 acc = make_float2(0.f, 0.f);
    float hs = 0.f;
    for (int e = 0; e < deg; e++) {
        int4 ent = g_csr[start + e];
        float h = __int_as_float(ent.z);
        hs += h;
        float2 zv = *reinterpret_cast<const float2*>(
            &g_z[(size_t)ent.x * NH + lane * 2]);
        acc.x = fmaf(h, zv.x, acc.x);
        acc.y = fmaf(h, zv.y, acc.y);
    }
    float inv = (hs != 0.f) ? (1.f / hs) : 0.f;
    *reinterpret_cast<float2*>(&out[(size_t)w * NH + lane * 2]) =
        make_float2(acc.x * inv, acc.y * inv);

    for (int e = lane; e < deg; e += 32) {
        int4 ent = g_csr[start + e];
        alpha[ent.y] = __int_as_float(ent.z) * inv;
    }
}

// ---------------------------------------------------------------------------
extern "C" void kernel_launch(void* const* d_in, const int* in_sizes, int n_in,
                              void* d_out, int out_size)
{
    const float* x  = (const float*)d_in[0];
    const void*  ei = d_in[1];
    const float* W  = (const float*)d_in[2];
    const float* aw = (const float*)d_in[3];
    const float* ab = (const float*)d_in[4];

    const int n_nodes = in_sizes[0] / NF;
    const int E       = in_sizes[1] / 2;
    const int nb      = (n_nodes + 255) / 256;

    float* out   = (float*)d_out;
    float* alpha = out + (size_t)n_nodes * NH;

    static int smem_set = 0;
    if (!smem_set) {
        cudaFuncSetAttribute(gemm_tc_kernel,
                             cudaFuncAttributeMaxDynamicSharedMemorySize,
                             SMEM_FLOATS * sizeof(float));
        smem_set = 1;
    }

    zero_kernel<<<(n_nodes + 1023) / 1024, 1024>>>(n_nodes);
    detect_kernel<<<1, 256>>>((const int*)ei, in_sizes[1]);
    w_split_kernel<<<(NF * NH + 255) / 256, 256>>>(W);
    convert_kernel<<<(E + 255) / 256, 256>>>(ei, E);

    gemm_tc_kernel<<<(n_nodes + 63) / 64, 256,
                     SMEM_FLOATS * sizeof(float)>>>(x, aw, n_nodes);

    scanA<<<nb, 256>>>(n_nodes);
    scanB<<<1, 256>>>(nb);
    scanC<<<nb, 256>>>(n_nodes);

    edge_scatter_kernel<<<(E + 255) / 256, 256>>>(ab, E);

    long long tot = (long long)n_nodes * 32;
    aggregate_csr_kernel<<<(int)((tot + 255) / 256), 256>>>(out, alpha, n_nodes);
}

// round 8
// speedup vs baseline: 1.0408x; 1.0408x over previous
#include <cuda_runtime.h>
#include <cstdint>

#define NF 128
#define NH 64
#define MAXN 50000
#define MAXE 800000

// Scratch (allocation-free rule: __device__ globals)
__device__ float g_z[(size_t)MAXN * NH];   // 12.8 MB
__device__ float g_sd[MAXN];
__device__ float g_ss[MAXN];
__device__ int   g_dst[MAXE];
__device__ int   g_src[MAXE];
__device__ int   g_cnt[MAXN];
__device__ int   g_rowstart[MAXN];
__device__ int   g_cursor[MAXN];
__device__ int   g_bsum[1024];
__device__ int4  g_csr[MAXE];              // {src, eidx, h_bits, 0}
__device__ int   g_is32;

// ---------------------------------------------------------------------------
__global__ void zero_kernel(int n_nodes) {
    int i = blockIdx.x * blockDim.x + threadIdx.x;
    if (i < n_nodes) g_cnt[i] = 0;
    if (i == 0) g_is32 = 0;
}

// dtype probe: scan first 4096 odd words; int64 (<2^31 values) -> all zero.
__global__ void detect_kernel(const int* __restrict__ w, int nelem) {
    int found = 0;
    int lim = nelem / 2;
    if (lim > 4096) lim = 4096;
    for (int i = threadIdx.x; i < lim; i += 256)
        found |= w[2 * i + 1];
    if (__syncthreads_or(found) && threadIdx.x == 0) g_is32 = 1;
}

// Convert to int32 + histogram, 4 edges per thread, vector loads/stores.
__global__ void convert_kernel(const void* __restrict__ ei, int E) {
    int t = blockIdx.x * blockDim.x + threadIdx.x;
    int base = t * 4;
    if (base >= E) return;
    int4 d4, s4;
    if (base + 3 < E && (E & 3) == 0) {
        if (g_is32) {
            const int4* p = (const int4*)ei;
            d4 = p[base >> 2];
            s4 = p[(E + base) >> 2];
        } else {
            const longlong2* p = (const longlong2*)ei;
            longlong2 a = p[base >> 1], b = p[(base >> 1) + 1];
            longlong2 c = p[(E + base) >> 1], d = p[(E + base) >> 1 + 0 ? (E + base) >> 1 : 0];
            d = p[((E + base) >> 1) + 1];
            d4 = make_int4((int)a.x, (int)a.y, (int)b.x, (int)b.y);
            s4 = make_int4((int)c.x, (int)c.y, (int)d.x, (int)d.y);
        }
        *reinterpret_cast<int4*>(&g_dst[base]) = d4;
        *reinterpret_cast<int4*>(&g_src[base]) = s4;
        atomicAdd(&g_cnt[d4.x], 1);
        atomicAdd(&g_cnt[d4.y], 1);
        atomicAdd(&g_cnt[d4.z], 1);
        atomicAdd(&g_cnt[d4.w], 1);
    } else {
        for (int i = base; i < E && i < base + 4; i++) {
            int d, s;
            if (g_is32) {
                const int* p = (const int*)ei;
                d = p[i]; s = p[E + i];
            } else {
                const long long* p = (const long long*)ei;
                d = (int)p[i]; s = (int)p[E + i];
            }
            g_dst[i] = d;
            g_src[i] = s;
            atomicAdd(&g_cnt[d], 1);
        }
    }
}

// ---------------------------------------------------------------------------
// Exclusive scan of g_cnt -> g_rowstart.
__global__ void scanA(int n) {
    __shared__ int s[256];
    int t = threadIdx.x, i = blockIdx.x * 256 + t;
    s[t] = (i < n) ? g_cnt[i] : 0;
    __syncthreads();
    for (int off = 128; off; off >>= 1) {
        if (t < off) s[t] += s[t + off];
        __syncthreads();
    }
    if (t == 0) g_bsum[blockIdx.x] = s[0];
}

__global__ void scanB(int nb) {
    __shared__ int s[256];
    int t = threadIdx.x;
    int v = (t < nb) ? g_bsum[t] : 0;
    s[t] = v; __syncthreads();
    for (int off = 1; off < 256; off <<= 1) {
        int a = (t >= off) ? s[t - off] : 0;
        __syncthreads();
        s[t] += a;
        __syncthreads();
    }
    if (t < nb) g_bsum[t] = s[t] - v;
}

__global__ void scanC(int n) {
    __shared__ int s[256];
    int t = threadIdx.x, i = blockIdx.x * 256 + t;
    int v = (i < n) ? g_cnt[i] : 0;
    s[t] = v; __syncthreads();
    for (int off = 1; off < 256; off <<= 1) {
        int a = (t >= off) ? s[t - off] : 0;
        __syncthreads();
        s[t] += a;
        __syncthreads();
    }
    if (i < n) {
        int start = g_bsum[blockIdx.x] + s[t] - v;
        g_rowstart[i] = start;
        g_cursor[i]   = start;
    }
}

// ---------------------------------------------------------------------------
// SIMT GEMM v2: 128x64 tile, 256 threads, 4 rows x 8 cols per thread.
// Per k: 4 scalar x-LDS + 2 W-LDS.128 feed 32 FMAs (vs 5 LDS / 16 FMA before).
// K chunked at 32: smem = xs[128][36] (18.4KB) + Ws[32][68] (8.7KB) = 27.1KB.
#define XS_STRIDE 36
#define WS_STRIDE 68

__global__ void __launch_bounds__(256) gemm_kernel(
    const float* __restrict__ x, const float* __restrict__ W,
    const float* __restrict__ aw, int n_nodes)
{
    __shared__ float xs[128 * XS_STRIDE];
    __shared__ float Ws[32 * WS_STRIDE];

    const int tid = threadIdx.x;
    const int tx  = tid & 7;               // 8 col groups of 8
    const int ty  = tid >> 3;              // 32 row groups of 4
    const int row0 = blockIdx.x * 128;

    float acc[4][8];
#pragma unroll
    for (int i = 0; i < 4; i++)
#pragma unroll
        for (int j = 0; j < 8; j++) acc[i][j] = 0.f;

    for (int kc = 0; kc < NF; kc += 32) {
        // x tile: 128 rows x 32 k = 1024 float4, 4 per thread
#pragma unroll
        for (int it = 0; it < 4; it++) {
            int i = tid + it * 256;
            int r = i >> 3, q = (i & 7) << 2;
            int row = row0 + r;
            float4 v = make_float4(0.f, 0.f, 0.f, 0.f);
            if (row < n_nodes)
                v = *reinterpret_cast<const float4*>(&x[(size_t)row * NF + kc + q]);
            *reinterpret_cast<float4*>(&xs[r * XS_STRIDE + q]) = v;
        }
        // W tile: 32 k x 64 cols = 512 float4, 2 per thread
#pragma unroll
        for (int it = 0; it < 2; it++) {
            int i = tid + it * 256;
            int k = i >> 4, q = (i & 15) << 2;
            *reinterpret_cast<float4*>(&Ws[k * WS_STRIDE + q]) =
                *reinterpret_cast<const float4*>(&W[(size_t)(kc + k) * NH + q]);
        }
        __syncthreads();

#pragma unroll 8
        for (int k = 0; k < 32; k++) {
            float4 w0 = *reinterpret_cast<const float4*>(&Ws[k * WS_STRIDE + tx * 8]);
            float4 w1 = *reinterpret_cast<const float4*>(&Ws[k * WS_STRIDE + tx * 8 + 4]);
#pragma unroll
            for (int i = 0; i < 4; i++) {
                float xv = xs[(ty * 4 + i) * XS_STRIDE + k];
                acc[i][0] = fmaf(xv, w0.x, acc[i][0]);
                acc[i][1] = fmaf(xv, w0.y, acc[i][1]);
                acc[i][2] = fmaf(xv, w0.z, acc[i][2]);
                acc[i][3] = fmaf(xv, w0.w, acc[i][3]);
                acc[i][4] = fmaf(xv, w1.x, acc[i][4]);
                acc[i][5] = fmaf(xv, w1.y, acc[i][5]);
                acc[i][6] = fmaf(xv, w1.z, acc[i][6]);
                acc[i][7] = fmaf(xv, w1.w, acc[i][7]);
            }
        }
        __syncthreads();
    }

    // scores: per-thread partial over 8 cols, reduce across tx (width 8)
    float a1[8], a2[8];
#pragma unroll
    for (int j = 0; j < 8; j++) {
        a1[j] = __ldg(&aw[tx * 8 + j]);
        a2[j] = __ldg(&aw[NH + tx * 8 + j]);
    }

#pragma unroll
    for (int i = 0; i < 4; i++) {
        int row = row0 + ty * 4 + i;
        float sd = 0.f, ss = 0.f;
#pragma unroll
        for (int j = 0; j < 8; j++) {
            sd = fmaf(acc[i][j], a1[j], sd);
            ss = fmaf(acc[i][j], a2[j], ss);
        }
#pragma unroll
        for (int off = 4; off; off >>= 1) {
            sd += __shfl_down_sync(0xffffffffu, sd, off, 8);
            ss += __shfl_down_sync(0xffffffffu, ss, off, 8);
        }
        if (row < n_nodes) {
            *reinterpret_cast<float4*>(&g_z[(size_t)row * NH + tx * 8]) =
                make_float4(acc[i][0], acc[i][1], acc[i][2], acc[i][3]);
            *reinterpret_cast<float4*>(&g_z[(size_t)row * NH + tx * 8 + 4]) =
                make_float4(acc[i][4], acc[i][5], acc[i][6], acc[i][7]);
            if (tx == 0) { g_sd[row] = sd; g_ss[row] = ss; }
        }
    }
}

// ---------------------------------------------------------------------------
__global__ void edge_scatter_kernel(const float* __restrict__ ab, int E) {
    int e = blockIdx.x * blockDim.x + threadIdx.x;
    if (e >= E) return;
    int d = g_dst[e], s = g_src[e];
    float h = g_sd[d] + g_ss[s] + __ldg(ab);
    h = (h >= 0.f) ? h : 0.05f * h;
    h = expf(h);
    int pos = atomicAdd(&g_cursor[d], 1);
    g_csr[pos] = make_int4(s, e, __float_as_int(h), 0);
}

// ---------------------------------------------------------------------------
__global__ void __launch_bounds__(256) aggregate_csr_kernel(
    float* __restrict__ out, float* __restrict__ alpha, int n_nodes)
{
    int w = (blockIdx.x * 256 + threadIdx.x) >> 5;
    int lane = threadIdx.x & 31;
    if (w >= n_nodes) return;

    int start = g_rowstart[w];
    int deg   = g_cnt[w];

    float2 acc = make_float2(0.f, 0.f);
    float hs = 0.f;
    for (int e = 0; e < deg; e++) {
        int4 ent = g_csr[start + e];
        float h = __int_as_float(ent.z);
        hs += h;
        float2 zv = *reinterpret_cast<const float2*>(
            &g_z[(size_t)ent.x * NH + lane * 2]);
        acc.x = fmaf(h, zv.x, acc.x);
        acc.y = fmaf(h, zv.y, acc.y);
    }
    float inv = (hs != 0.f) ? (1.f / hs) : 0.f;
    *reinterpret_cast<float2*>(&out[(size_t)w * NH + lane * 2]) =
        make_float2(acc.x * inv, acc.y * inv);

    for (int e = lane; e < deg; e += 32) {
        int4 ent = g_csr[start + e];
        alpha[ent.y] = __int_as_float(ent.z) * inv;
    }
}

// ---------------------------------------------------------------------------
extern "C" void kernel_launch(void* const* d_in, const int* in_sizes, int n_in,
                              void* d_out, int out_size)
{
    const float* x  = (const float*)d_in[0];
    const void*  ei = d_in[1];
    const float* W  = (const float*)d_in[2];
    const float* aw = (const float*)d_in[3];
    const float* ab = (const float*)d_in[4];

    const int n_nodes = in_sizes[0] / NF;
    const int E       = in_sizes[1] / 2;
    const int nb      = (n_nodes + 255) / 256;

    float* out   = (float*)d_out;
    float* alpha = out + (size_t)n_nodes * NH;

    zero_kernel<<<(n_nodes + 1023) / 1024, 1024>>>(n_nodes);
    detect_kernel<<<1, 256>>>((const int*)ei, in_sizes[1]);
    convert_kernel<<<(E / 4 + 255) / 256, 256>>>(ei, E);

    gemm_kernel<<<(n_nodes + 127) / 128, 256>>>(x, W, aw, n_nodes);

    scanA<<<nb, 256>>>(n_nodes);
    scanB<<<1, 256>>>(nb);
    scanC<<<nb, 256>>>(n_nodes);

    edge_scatter_kernel<<<(E + 255) / 256, 256>>>(ab, E);

    long long tot = (long long)n_nodes * 32;
    aggregate_csr_kernel<<<(int)((tot + 255) / 256), 256>>>(out, alpha, n_nodes);
}

// round 10
// speedup vs baseline: 1.1387x; 1.0940x over previous
#include <cuda_runtime.h>
#include <cuda_fp16.h>
#include <cstdint>

#define NF 128
#define NH 64
#define MAXN 50000
#define MAXE 800000

// Scratch (allocation-free rule: __device__ globals)
__device__ __half2 g_zh[(size_t)MAXN * (NH / 2)];   // 6.4 MB, z in fp16
__device__ float g_sd[MAXN];
__device__ float g_ss[MAXN];
__device__ int   g_dst[MAXE];
__device__ int   g_src[MAXE];
__device__ int   g_cnt[MAXN];
__device__ int   g_rowstart[MAXN];
__device__ int   g_cursor[MAXN];
__device__ int   g_bsum[1024];
__device__ int4  g_csr[MAXE];              // {src, eidx, h_bits, 0}
__device__ int   g_is32;

// ---------------------------------------------------------------------------
__global__ void zero_kernel(int n_nodes) {
    int i = blockIdx.x * blockDim.x + threadIdx.x;
    if (i < n_nodes) g_cnt[i] = 0;
    if (i == 0) g_is32 = 0;
}

// dtype probe: scan first 4096 odd words; int64 (<2^31 values) -> all zero.
__global__ void detect_kernel(const int* __restrict__ w, int nelem) {
    int found = 0;
    int lim = nelem / 2;
    if (lim > 4096) lim = 4096;
    for (int i = threadIdx.x; i < lim; i += 256)
        found |= w[2 * i + 1];
    if (__syncthreads_or(found) && threadIdx.x == 0) g_is32 = 1;
}

// Convert to int32 + histogram, 4 edges per thread, vector loads/stores.
__global__ void convert_kernel(const void* __restrict__ ei, int E) {
    int t = blockIdx.x * blockDim.x + threadIdx.x;
    int base = t * 4;
    if (base >= E) return;
    if (base + 3 < E && (E & 3) == 0) {
        int4 d4, s4;
        if (g_is32) {
            const int4* p = (const int4*)ei;
            d4 = p[base >> 2];
            s4 = p[(E + base) >> 2];
        } else {
            const longlong2* p = (const longlong2*)ei;
            longlong2 a0 = p[(base >> 1)];
            longlong2 a1 = p[(base >> 1) + 1];
            longlong2 b0 = p[((E + base) >> 1)];
            longlong2 b1 = p[((E + base) >> 1) + 1];
            d4 = make_int4((int)a0.x, (int)a0.y, (int)a1.x, (int)a1.y);
            s4 = make_int4((int)b0.x, (int)b0.y, (int)b1.x, (int)b1.y);
        }
        *reinterpret_cast<int4*>(&g_dst[base]) = d4;
        *reinterpret_cast<int4*>(&g_src[base]) = s4;
        atomicAdd(&g_cnt[d4.x], 1);
        atomicAdd(&g_cnt[d4.y], 1);
        atomicAdd(&g_cnt[d4.z], 1);
        atomicAdd(&g_cnt[d4.w], 1);
    } else {
        for (int i = base; i < E && i < base + 4; i++) {
            int d, s;
            if (g_is32) {
                const int* p = (const int*)ei;
                d = p[i]; s = p[E + i];
            } else {
                const long long* p = (const long long*)ei;
                d = (int)p[i]; s = (int)p[E + i];
            }
            g_dst[i] = d;
            g_src[i] = s;
            atomicAdd(&g_cnt[d], 1);
        }
    }
}

// ---------------------------------------------------------------------------
// Exclusive scan of g_cnt -> g_rowstart.
__global__ void scanA(int n) {
    __shared__ int s[256];
    int t = threadIdx.x, i = blockIdx.x * 256 + t;
    s[t] = (i < n) ? g_cnt[i] : 0;
    __syncthreads();
    for (int off = 128; off; off >>= 1) {
        if (t < off) s[t] += s[t + off];
        __syncthreads();
    }
    if (t == 0) g_bsum[blockIdx.x] = s[0];
}

__global__ void scanB(int nb) {
    __shared__ int s[256];
    int t = threadIdx.x;
    int v = (t < nb) ? g_bsum[t] : 0;
    s[t] = v; __syncthreads();
    for (int off = 1; off < 256; off <<= 1) {
        int a = (t >= off) ? s[t - off] : 0;
        __syncthreads();
        s[t] += a;
        __syncthreads();
    }
    if (t < nb) g_bsum[t] = s[t] - v;
}

__global__ void scanC(int n) {
    __shared__ int s[256];
    int t = threadIdx.x, i = blockIdx.x * 256 + t;
    int v = (i < n) ? g_cnt[i] : 0;
    s[t] = v; __syncthreads();
    for (int off = 1; off < 256; off <<= 1) {
        int a = (t >= off) ? s[t - off] : 0;
        __syncthreads();
        s[t] += a;
        __syncthreads();
    }
    if (i < n) {
        int start = g_bsum[blockIdx.x] + s[t] - v;
        g_rowstart[i] = start;
        g_cursor[i]   = start;
    }
}

// ---------------------------------------------------------------------------
// Register-tiled GEMM (round-2 proven config): 64x64 tile, 4x4 per thread,
// fused score reduction; z stored as fp16 half2 (consumed only by aggregate).
__global__ void __launch_bounds__(256) gemm_kernel(
    const float* __restrict__ x, const float* __restrict__ W,
    const float* __restrict__ aw, int n_nodes)
{
    __shared__ float xs[64][64];
    __shared__ float Ws[64][64];

    const int tid = threadIdx.x;
    const int tx  = tid & 15;
    const int ty  = tid >> 4;
    const int row0 = blockIdx.x * 64;

    float acc[4][4];
#pragma unroll
    for (int i = 0; i < 4; i++)
#pragma unroll
        for (int j = 0; j < 4; j++) acc[i][j] = 0.f;

    for (int kc = 0; kc < NF; kc += 64) {
#pragma unroll
        for (int it = 0; it < 4; it++) {
            int i = tid + it * 256;
            int r = i >> 4, q = (i & 15) << 2;
            int row = row0 + r;
            float4 v = make_float4(0.f, 0.f, 0.f, 0.f);
            if (row < n_nodes)
                v = *reinterpret_cast<const float4*>(&x[(size_t)row * NF + kc + q]);
            *reinterpret_cast<float4*>(&xs[r][q]) = v;
        }
#pragma unroll
        for (int it = 0; it < 4; it++) {
            int i = tid + it * 256;
            int k = i >> 4, q = (i & 15) << 2;
            *reinterpret_cast<float4*>(&Ws[k][q]) =
                *reinterpret_cast<const float4*>(&W[(size_t)(kc + k) * NH + q]);
        }
        __syncthreads();

#pragma unroll
        for (int k = 0; k < 64; k++) {
            float4 wv = *reinterpret_cast<const float4*>(&Ws[k][tx << 2]);
            float x0 = xs[(ty << 2) + 0][k];
            float x1 = xs[(ty << 2) + 1][k];
            float x2 = xs[(ty << 2) + 2][k];
            float x3 = xs[(ty << 2) + 3][k];
            acc[0][0] = fmaf(x0, wv.x, acc[0][0]); acc[0][1] = fmaf(x0, wv.y, acc[0][1]);
            acc[0][2] = fmaf(x0, wv.z, acc[0][2]); acc[0][3] = fmaf(x0, wv.w, acc[0][3]);
            acc[1][0] = fmaf(x1, wv.x, acc[1][0]); acc[1][1] = fmaf(x1, wv.y, acc[1][1]);
            acc[1][2] = fmaf(x1, wv.z, acc[1][2]); acc[1][3] = fmaf(x1, wv.w, acc[1][3]);
            acc[2][0] = fmaf(x2, wv.x, acc[2][0]); acc[2][1] = fmaf(x2, wv.y, acc[2][1]);
            acc[2][2] = fmaf(x2, wv.z, acc[2][2]); acc[2][3] = fmaf(x2, wv.w, acc[2][3]);
            acc[3][0] = fmaf(x3, wv.x, acc[3][0]); acc[3][1] = fmaf(x3, wv.y, acc[3][1]);
            acc[3][2] = fmaf(x3, wv.z, acc[3][2]); acc[3][3] = fmaf(x3, wv.w, acc[3][3]);
        }
        __syncthreads();
    }

    const float4 a1 = *reinterpret_cast<const float4*>(&aw[tx << 2]);
    const float4 a2 = *reinterpret_cast<const float4*>(&aw[NH + (tx << 2)]);

#pragma unroll
    for (int i = 0; i < 4; i++) {
        int row = row0 + (ty << 2) + i;
        float sd = acc[i][0] * a1.x + acc[i][1] * a1.y + acc[i][2] * a1.z + acc[i][3] * a1.w;
        float ss = acc[i][0] * a2.x + acc[i][1] * a2.y + acc[i][2] * a2.z + acc[i][3] * a2.w;
#pragma unroll
        for (int off = 8; off; off >>= 1) {
            sd += __shfl_down_sync(0xffffffffu, sd, off, 16);
            ss += __shfl_down_sync(0xffffffffu, ss, off, 16);
        }
        if (row < n_nodes) {
            __half2 hp[2];
            hp[0] = __floats2half2_rn(acc[i][0], acc[i][1]);
            hp[1] = __floats2half2_rn(acc[i][2], acc[i][3]);
            *reinterpret_cast<float2*>(&g_zh[(size_t)row * 32 + (tx << 1)]) =
                *reinterpret_cast<const float2*>(hp);
            if (tx == 0) { g_sd[row] = sd; g_ss[row] = ss; }
        }
    }
}

// ---------------------------------------------------------------------------
__global__ void edge_scatter_kernel(const float* __restrict__ ab, int E) {
    int e = blockIdx.x * blockDim.x + threadIdx.x;
    if (e >= E) return;
    int d = g_dst[e], s = g_src[e];
    float h = g_sd[d] + g_ss[s] + __ldg(ab);
    h = (h >= 0.f) ? h : 0.05f * h;
    h = expf(h);
    int pos = atomicAdd(&g_cursor[d], 1);
    g_csr[pos] = make_int4(s, e, __float_as_int(h), 0);
}

// ---------------------------------------------------------------------------
// One warp per dst node, z gathered as half2 (half the L2 bytes).
__global__ void __launch_bounds__(256) aggregate_csr_kernel(
    float* __restrict__ out, float* __restrict__ alpha, int n_nodes)
{
    int w = (blockIdx.x * 256 + threadIdx.x) >> 5;
    int lane = threadIdx.x & 31;
    if (w >= n_nodes) return;

    int start = g_rowstart[w];
    int deg   = g_cnt[w];

    float2 acc = make_float2(0.f, 0.f);
    float hs = 0.f;
    for (int e = 0; e < deg; e++) {
        int4 ent = g_csr[start + e];            // broadcast, 1 sector
        float h = __int_as_float(ent.z);
        hs += h;
        __half2 zh = g_zh[(size_t)ent.x * 32 + lane];
        float2 zv = __half22float2(zh);
        acc.x = fmaf(h, zv.x, acc.x);
        acc.y = fmaf(h, zv.y, acc.y);
    }
    float inv = (hs != 0.f) ? (1.f / hs) : 0.f;
    *reinterpret_cast<float2*>(&out[(size_t)w * NH + lane * 2]) =
        make_float2(acc.x * inv, acc.y * inv);

    for (int e = lane; e < deg; e += 32) {
        int4 ent = g_csr[start + e];            // L1 hit
        alpha[ent.y] = __int_as_float(ent.z) * inv;
    }
}

// ---------------------------------------------------------------------------
extern "C" void kernel_launch(void* const* d_in, const int* in_sizes, int n_in,
                              void* d_out, int out_size)
{
    const float* x  = (const float*)d_in[0];
    const void*  ei = d_in[1];
    const float* W  = (const float*)d_in[2];
    const float* aw = (const float*)d_in[3];
    const float* ab = (const float*)d_in[4];

    const int n_nodes = in_sizes[0] / NF;
    const int E       = in_sizes[1] / 2;
    const int nb      = (n_nodes + 255) / 256;

    float* out   = (float*)d_out;
    float* alpha = out + (size_t)n_nodes * NH;

    zero_kernel<<<(n_nodes + 1023) / 1024, 1024>>>(n_nodes);
    detect_kernel<<<1, 256>>>((const int*)ei, in_sizes[1]);
    convert_kernel<<<(E / 4 + 255) / 256, 256>>>(ei, E);

    gemm_kernel<<<(n_nodes + 63) / 64, 256>>>(x, W, aw, n_nodes);

    scanA<<<nb, 256>>>(n_nodes);
    scanB<<<1, 256>>>(nb);
    scanC<<<nb, 256>>>(n_nodes);

    edge_scatter_kernel<<<(E + 255) / 256, 256>>>(ab, E);

    long long tot = (long long)n_nodes * 32;
    aggregate_csr_kernel<<<(int)((tot + 255) / 256), 256>>>(out, alpha, n_nodes);
}